// round 2
// baseline (speedup 1.0000x reference)
#include <cuda_runtime.h>
#include <cuda_bf16.h>

// Problem constants (fixed shapes)
#define B_  32
#define T_  512
#define D_  256
#define F_  256
#define KK_ 768          // D_*3 (im2col K dim)
#define MELMAX_ 2304
#define TT 32            // t-tile per conv block
#define GT 8             // t_out per gather block

// Scratch (no cudaMalloc allowed)
__device__ float g_h1[B_ * T_ * F_];
__device__ float g_h2[B_ * T_ * F_];
__device__ float g_wt1[KK_ * F_];
__device__ float g_wt2[KK_ * F_];
__device__ int   g_cum[B_ * T_];

// ---------------------------------------------------------------------------
// Weight transpose: w[f][d][k] -> wt[(k*256+d)][f]   (coalesced over f)
// ---------------------------------------------------------------------------
__global__ void transpose_w_kernel(const float* __restrict__ w, float* __restrict__ wt) {
    int idx = blockIdx.x * 256 + threadIdx.x;    // idx = kk*256 + f
    if (idx < KK_ * F_) {
        int f = idx & 255;
        int kk = idx >> 8;       // 0..767
        int d = kk & 255;
        int k = kk >> 8;         // 0..2
        wt[idx] = w[(f * D_ + d) * 3 + k];
    }
}

// ---------------------------------------------------------------------------
// Inclusive cumsum of target durations per batch (512 threads / block)
// ---------------------------------------------------------------------------
__global__ void cumsum_kernel(const int* __restrict__ target, int* __restrict__ cum) {
    __shared__ int s[T_];
    int b = blockIdx.x, t = threadIdx.x;
    s[t] = target[b * T_ + t];
    __syncthreads();
    for (int off = 1; off < T_; off <<= 1) {
        int v = (t >= off) ? s[t - off] : 0;
        __syncthreads();
        s[t] += v;
        __syncthreads();
    }
    cum[b * T_ + t] = s[t];
}

// ---------------------------------------------------------------------------
// Fused conv1d(K=3, pad=1) + bias + LayerNorm(F) + ReLU
// grid: (T_/TT, B_), block: 256 threads (thread = output channel f)
// wt layout: [(k*256+d)][f]
// ---------------------------------------------------------------------------
__global__ __launch_bounds__(256) void conv_ln_relu_kernel(
    const float* __restrict__ in,    // [B,T,D]
    const float* __restrict__ wt,    // [768,256]
    const float* __restrict__ bias,  // [F]
    const float* __restrict__ gamma, // [F]
    const float* __restrict__ beta,  // [F]
    float* __restrict__ out)         // [B,T,F]
{
    __shared__ float xs[(TT + 2) * 256];   // x slab (rows t0-1 .. t0+TT), reused as value buf

    const int b = blockIdx.y;
    const int t0 = blockIdx.x * TT;
    const int f = threadIdx.x;
    const float* inb = in + (size_t)b * T_ * D_;

    // load x slab (zero-padded at sequence edges)
    #pragma unroll
    for (int r = 0; r < TT + 2; r++) {
        int tg = t0 + r - 1;
        xs[r * 256 + f] = (tg >= 0 && tg < T_) ? inb[tg * D_ + f] : 0.0f;
    }
    __syncthreads();

    float acc[TT];
    #pragma unroll
    for (int i = 0; i < TT; i++) acc[i] = 0.0f;

    for (int d = 0; d < 256; d++) {
        float w0 = wt[(0 * 256 + d) * 256 + f];
        float w1 = wt[(1 * 256 + d) * 256 + f];
        float w2 = wt[(2 * 256 + d) * 256 + f];
        float xv[TT + 2];
        #pragma unroll
        for (int r = 0; r < TT + 2; r++) xv[r] = xs[r * 256 + d];
        #pragma unroll
        for (int tt = 0; tt < TT; tt++) {
            acc[tt] += w0 * xv[tt];
            acc[tt] += w1 * xv[tt + 1];
            acc[tt] += w2 * xv[tt + 2];
        }
    }

    // add bias, stage to smem for cross-thread LayerNorm
    __syncthreads();
    float bval = bias[f];
    #pragma unroll
    for (int tt = 0; tt < TT; tt++) xs[tt * 256 + f] = acc[tt] + bval;
    __syncthreads();

    const int warp = threadIdx.x >> 5;
    const int lane = threadIdx.x & 31;

    // per-thread g/beta for its 8 f-slots
    float gv[8], bv[8];
    #pragma unroll
    for (int j = 0; j < 8; j++) {
        gv[j] = gamma[lane + j * 32];
        bv[j] = beta[lane + j * 32];
    }

    // 8 warps x 4 rows = 32 rows
    #pragma unroll
    for (int i = 0; i < TT / 8; i++) {
        int tt = warp * (TT / 8) + i;
        float s = 0.0f, s2 = 0.0f;
        float v[8];
        #pragma unroll
        for (int j = 0; j < 8; j++) {
            v[j] = xs[tt * 256 + lane + j * 32];
            s += v[j];
            s2 += v[j] * v[j];
        }
        #pragma unroll
        for (int o = 16; o; o >>= 1) {
            s  += __shfl_xor_sync(0xFFFFFFFFu, s, o);
            s2 += __shfl_xor_sync(0xFFFFFFFFu, s2, o);
        }
        float mu  = s * (1.0f / 256.0f);
        float var = s2 * (1.0f / 256.0f) - mu * mu;
        float inv = rsqrtf(var + 1e-5f);
        int t = t0 + tt;
        float* orow = out + ((size_t)b * T_ + t) * F_;
        #pragma unroll
        for (int j = 0; j < 8; j++) {
            float y = (v[j] - mu) * inv * gv[j] + bv[j];
            orow[lane + j * 32] = fmaxf(y, 0.0f);
        }
    }
}

// ---------------------------------------------------------------------------
// dur_pred = relu(h2 @ lin_w^T + lin_b); one warp per (b,t) row
// ---------------------------------------------------------------------------
__global__ void dur_kernel(const float* __restrict__ h, const float* __restrict__ lw,
                           const float* __restrict__ lb, float* __restrict__ dur) {
    int row = blockIdx.x * 8 + (threadIdx.x >> 5);
    int lane = threadIdx.x & 31;
    const float* hr = h + (size_t)row * F_;
    float s = 0.0f;
    #pragma unroll
    for (int j = 0; j < 8; j++) s += hr[lane + j * 32] * lw[lane + j * 32];
    #pragma unroll
    for (int o = 16; o; o >>= 1) s += __shfl_xor_sync(0xFFFFFFFFu, s, o);
    if (lane == 0) dur[row] = fmaxf(s + lb[0], 0.0f);
}

// ---------------------------------------------------------------------------
// Length-regulator gather: out[b,t_out,:] = (t_out < cum[b,511]) ? x[b,idx,:] : 0
// idx = upper_bound(cum[b,:], t_out)
// grid: (MELMAX/GT, B_), block: 256
// ---------------------------------------------------------------------------
__global__ void gather_kernel(const float* __restrict__ x, const int* __restrict__ cum,
                              float* __restrict__ out) {
    __shared__ int sc[T_];
    int b = blockIdx.y;
    int f = threadIdx.x;
    sc[f] = cum[b * T_ + f];
    sc[256 + f] = cum[b * T_ + 256 + f];
    __syncthreads();
    int total = sc[T_ - 1];
    int t0 = blockIdx.x * GT;
    #pragma unroll
    for (int i = 0; i < GT; i++) {
        int t = t0 + i;
        float v = 0.0f;
        if (t < total) {
            int lo = 0, hi = T_;
            while (lo < hi) {
                int mid = (lo + hi) >> 1;
                if (sc[mid] > t) hi = mid; else lo = mid + 1;
            }
            int j = min(lo, T_ - 1);
            v = x[((size_t)b * T_ + j) * D_ + f];
        }
        out[((size_t)b * MELMAX_ + t) * D_ + f] = v;
    }
}

// ---------------------------------------------------------------------------
extern "C" void kernel_launch(void* const* d_in, const int* in_sizes, int n_in,
                              void* d_out, int out_size) {
    // Input layout (metadata order): x, target, [mel_max_length], conv1_w, conv1_b,
    // ln1_g, ln1_b, conv2_w, conv2_b, ln2_g, ln2_b, lin_w, lin_b
    // mel_max_length is a scalar; detect whether it appears as an input.
    int base = 2;
    if (n_in >= 3 && in_sizes[2] == 1) base = 3;   // scalar mel_max_length present

    const float* x        = (const float*)d_in[0];
    const int*   target   = (const int*)  d_in[1];
    const float* conv1_w  = (const float*)d_in[base + 0];
    const float* conv1_b  = (const float*)d_in[base + 1];
    const float* ln1_g    = (const float*)d_in[base + 2];
    const float* ln1_b    = (const float*)d_in[base + 3];
    const float* conv2_w  = (const float*)d_in[base + 4];
    const float* conv2_b  = (const float*)d_in[base + 5];
    const float* ln2_g    = (const float*)d_in[base + 6];
    const float* ln2_b    = (const float*)d_in[base + 7];
    const float* lin_w    = (const float*)d_in[base + 8];
    const float* lin_b    = (const float*)d_in[base + 9];

    float* out_main = (float*)d_out;                                  // [B, MELMAX, D]
    float* out_dur  = (float*)d_out + (size_t)B_ * MELMAX_ * D_;      // [B, T]

    float *h1, *h2, *wt1, *wt2;
    int *cum;
    cudaGetSymbolAddress((void**)&h1,  g_h1);
    cudaGetSymbolAddress((void**)&h2,  g_h2);
    cudaGetSymbolAddress((void**)&wt1, g_wt1);
    cudaGetSymbolAddress((void**)&wt2, g_wt2);
    cudaGetSymbolAddress((void**)&cum, g_cum);

    // 1. transpose weights
    transpose_w_kernel<<<(KK_ * F_ + 255) / 256, 256>>>(conv1_w, wt1);
    transpose_w_kernel<<<(KK_ * F_ + 255) / 256, 256>>>(conv2_w, wt2);

    // 2. cumsum of durations
    cumsum_kernel<<<B_, T_>>>(target, cum);

    // 3. conv1 + LN + relu
    dim3 cgrid(T_ / TT, B_);
    conv_ln_relu_kernel<<<cgrid, 256>>>(x, wt1, conv1_b, ln1_g, ln1_b, h1);

    // 4. conv2 + LN + relu
    conv_ln_relu_kernel<<<cgrid, 256>>>(h1, wt2, conv2_b, ln2_g, ln2_b, h2);

    // 5. duration head
    dur_kernel<<<(B_ * T_) / 8, 256>>>(h2, lin_w, lin_b, out_dur);

    // 6. length-regulator gather
    dim3 ggrid(MELMAX_ / GT, B_);
    gather_kernel<<<ggrid, 256>>>(x, cum, out_main);
}

// round 3
// speedup vs baseline: 1.2868x; 1.2868x over previous
#include <cuda_runtime.h>
#include <cuda_bf16.h>

typedef unsigned long long ull;

// Problem constants (fixed shapes)
#define B_  32
#define T_  512
#define D_  256
#define F_  256
#define KK_ 768          // D_*3 (im2col K dim)
#define MELMAX_ 2304
#define TT 32            // t-tile per conv block
#define ROWP 34          // padded slab row length (even -> 8B-aligned even pairs)

// Scratch (no cudaMalloc allowed)
__device__ float g_h1[B_ * T_ * F_];
__device__ float g_wt1[KK_ * F_];
__device__ float g_wt2[KK_ * F_];
__device__ int   g_idx[B_ * MELMAX_];

// ---------------------------------------------------------------------------
// f32x2 helpers (sm_103a packed fp32 FMA)
// ---------------------------------------------------------------------------
static __device__ __forceinline__ ull pk2(float lo, float hi) {
    ull r; asm("mov.b64 %0, {%1, %2};" : "=l"(r) : "f"(lo), "f"(hi)); return r;
}
static __device__ __forceinline__ ull ffma2(ull a, ull b, ull c) {
    ull d; asm("fma.rn.f32x2 %0, %1, %2, %3;" : "=l"(d) : "l"(a), "l"(b), "l"(c)); return d;
}
// {hi(a), lo(b)}
static __device__ __forceinline__ ull mix2(ull a, ull b) {
    ull r;
    asm("{ .reg .b32 a0,a1,b0,b1;\n\t"
        "  mov.b64 {a0,a1}, %1;\n\t"
        "  mov.b64 {b0,b1}, %2;\n\t"
        "  mov.b64 %0, {a1,b0}; }"
        : "=l"(r) : "l"(a), "l"(b));
    return r;
}
static __device__ __forceinline__ void upk2(ull v, float& lo, float& hi) {
    asm("mov.b64 {%0, %1}, %2;" : "=f"(lo), "=f"(hi) : "l"(v));
}

// ---------------------------------------------------------------------------
// Weight transpose for BOTH conv layers: w[f][d][k] -> wt[(k*256+d)][f]
// ---------------------------------------------------------------------------
__global__ void transpose_w_kernel(const float* __restrict__ w1, float* __restrict__ wt1,
                                   const float* __restrict__ w2, float* __restrict__ wt2) {
    int half = (KK_ * F_) / 256;
    int blk = blockIdx.x;
    const float* w = (blk < half) ? w1 : w2;
    float* wt      = (blk < half) ? wt1 : wt2;
    if (blk >= half) blk -= half;
    int idx = blk * 256 + threadIdx.x;   // idx = kk*256 + f
    int f = idx & 255;
    int kk = idx >> 8;                   // 0..767
    int d = kk & 255;
    int k = kk >> 8;                     // 0..2
    wt[idx] = w[(f * D_ + d) * 3 + k];
}

// ---------------------------------------------------------------------------
// Cumsum of durations + expansion to per-t_out source index (or -1 past end)
// 512 threads / block, one block per batch
// ---------------------------------------------------------------------------
__global__ void cumsum_idx_kernel(const int* __restrict__ target, int* __restrict__ idx) {
    __shared__ int s[T_];
    int b = blockIdx.x, t = threadIdx.x;
    s[t] = target[b * T_ + t];
    __syncthreads();
    for (int off = 1; off < T_; off <<= 1) {
        int v = (t >= off) ? s[t - off] : 0;
        __syncthreads();
        s[t] += v;
        __syncthreads();
    }
    int hi = s[t];
    int lo = (t > 0) ? s[t - 1] : 0;
    int* ib = idx + b * MELMAX_;
    for (int p = lo; p < hi && p < MELMAX_; p++) ib[p] = t;
    int total = s[T_ - 1];
    for (int p = total + t; p < MELMAX_; p += T_) ib[p] = -1;
}

// ---------------------------------------------------------------------------
// Fused conv1d(K=3, pad=1) + bias + LayerNorm(F) + ReLU  [+ optional dur head]
// grid: (T_/TT, B_), block: 256 (thread = output channel f)
// wt layout: [(k*256+d)][f].  FFMA2 over t-pairs, d-major smem slab.
// ---------------------------------------------------------------------------
template <bool DUR>
__global__ __launch_bounds__(256) void conv_ln_relu_kernel(
    const float* __restrict__ in,    // [B,T,D]
    const float* __restrict__ wt,    // [768,256]
    const float* __restrict__ bias,  // [F]
    const float* __restrict__ gamma, // [F]
    const float* __restrict__ beta,  // [F]
    const float* __restrict__ lw,    // [F]   (DUR only)
    const float* __restrict__ lb,    // [1]   (DUR only)
    float* __restrict__ out)         // [B,T,F] or dur [B,T]
{
    __shared__ alignas(16) float sm[D_ * ROWP];   // d-major x slab; reused as LN stage

    const int b = blockIdx.y;
    const int t0 = blockIdx.x * TT;
    const int f = threadIdx.x;
    const float* inb = in + (size_t)b * T_ * D_;

    // load x slab transposed: sm[d*ROWP + r] = x[t0+r-1][d]   (thread f owns column d=f)
    {
        float* col = sm + f * ROWP;
        #pragma unroll
        for (int r = 0; r < TT + 2; r++) {
            int tg = t0 + r - 1;
            col[r] = (tg >= 0 && tg < T_) ? inb[tg * D_ + f] : 0.0f;
        }
    }
    __syncthreads();

    ull acc[TT / 2];
    #pragma unroll
    for (int i = 0; i < TT / 2; i++) acc[i] = 0ull;

    for (int d = 0; d < D_; d++) {
        const float* col = sm + d * ROWP;
        ull pe[TT / 2 + 1];
        #pragma unroll
        for (int i = 0; i <= TT / 2; i++) pe[i] = *(const ull*)(col + 2 * i);
        float w0 = wt[(0 * 256 + d) * 256 + f];
        float w1 = wt[(1 * 256 + d) * 256 + f];
        float w2 = wt[(2 * 256 + d) * 256 + f];
        ull ww0 = pk2(w0, w0), ww1 = pk2(w1, w1), ww2 = pk2(w2, w2);
        #pragma unroll
        for (int i = 0; i < TT / 2; i++) {
            ull po = mix2(pe[i], pe[i + 1]);
            acc[i] = ffma2(ww0, pe[i], acc[i]);
            acc[i] = ffma2(ww1, po, acc[i]);
            acc[i] = ffma2(ww2, pe[i + 1], acc[i]);
        }
    }

    // stage (bias added) for cross-thread LayerNorm
    __syncthreads();
    {
        float bval = bias[f];
        #pragma unroll
        for (int i = 0; i < TT / 2; i++) {
            float lo, hi;
            upk2(acc[i], lo, hi);
            sm[(2 * i) * 256 + f]     = lo + bval;
            sm[(2 * i + 1) * 256 + f] = hi + bval;
        }
    }
    __syncthreads();

    const int warp = threadIdx.x >> 5;
    const int lane = threadIdx.x & 31;

    float gv[8], bv[8], lwv[8];
    #pragma unroll
    for (int j = 0; j < 8; j++) {
        gv[j] = gamma[lane + j * 32];
        bv[j] = beta[lane + j * 32];
        if (DUR) lwv[j] = lw[lane + j * 32];
    }
    float lbv = DUR ? lb[0] : 0.0f;

    // 8 warps x 4 rows = 32 rows
    #pragma unroll
    for (int i = 0; i < TT / 8; i++) {
        int tt = warp * (TT / 8) + i;
        float s = 0.0f, s2 = 0.0f;
        float v[8];
        #pragma unroll
        for (int j = 0; j < 8; j++) {
            v[j] = sm[tt * 256 + lane + j * 32];
            s += v[j];
            s2 += v[j] * v[j];
        }
        #pragma unroll
        for (int o = 16; o; o >>= 1) {
            s  += __shfl_xor_sync(0xFFFFFFFFu, s, o);
            s2 += __shfl_xor_sync(0xFFFFFFFFu, s2, o);
        }
        float mu  = s * (1.0f / 256.0f);
        float var = s2 * (1.0f / 256.0f) - mu * mu;
        float inv = rsqrtf(var + 1e-5f);
        int t = t0 + tt;
        if (DUR) {
            float sd = 0.0f;
            #pragma unroll
            for (int j = 0; j < 8; j++) {
                float y = fmaxf((v[j] - mu) * inv * gv[j] + bv[j], 0.0f);
                sd += y * lwv[j];
            }
            #pragma unroll
            for (int o = 16; o; o >>= 1) sd += __shfl_xor_sync(0xFFFFFFFFu, sd, o);
            if (lane == 0) out[(size_t)b * T_ + t] = fmaxf(sd + lbv, 0.0f);
        } else {
            float* orow = out + ((size_t)b * T_ + t) * F_;
            #pragma unroll
            for (int j = 0; j < 8; j++) {
                float y = (v[j] - mu) * inv * gv[j] + bv[j];
                orow[lane + j * 32] = fmaxf(y, 0.0f);
            }
        }
    }
}

// ---------------------------------------------------------------------------
// Length-regulator gather via precomputed idx (float4 streaming)
// block: 256 threads = 64 f-quads x 4 rows; each block does 16 t_out rows
// ---------------------------------------------------------------------------
__global__ __launch_bounds__(256) void gather_kernel(
    const float4* __restrict__ x4, const int* __restrict__ idx, float4* __restrict__ out4) {
    const int b = blockIdx.y;
    const int f4 = threadIdx.x & 63;
    const int trow = threadIdx.x >> 6;
    const int t0 = blockIdx.x * 16;
    const float4 z = make_float4(0.f, 0.f, 0.f, 0.f);
    #pragma unroll
    for (int i = 0; i < 4; i++) {
        int t = t0 + i * 4 + trow;
        int j = idx[b * MELMAX_ + t];
        float4 v = (j >= 0) ? x4[((size_t)b * T_ + j) * 64 + f4] : z;
        out4[((size_t)b * MELMAX_ + t) * 64 + f4] = v;
    }
}

// ---------------------------------------------------------------------------
extern "C" void kernel_launch(void* const* d_in, const int* in_sizes, int n_in,
                              void* d_out, int out_size) {
    int base = 2;
    if (n_in >= 3 && in_sizes[2] == 1) base = 3;   // scalar mel_max_length present

    const float* x        = (const float*)d_in[0];
    const int*   target   = (const int*)  d_in[1];
    const float* conv1_w  = (const float*)d_in[base + 0];
    const float* conv1_b  = (const float*)d_in[base + 1];
    const float* ln1_g    = (const float*)d_in[base + 2];
    const float* ln1_b    = (const float*)d_in[base + 3];
    const float* conv2_w  = (const float*)d_in[base + 4];
    const float* conv2_b  = (const float*)d_in[base + 5];
    const float* ln2_g    = (const float*)d_in[base + 6];
    const float* ln2_b    = (const float*)d_in[base + 7];
    const float* lin_w    = (const float*)d_in[base + 8];
    const float* lin_b    = (const float*)d_in[base + 9];

    float* out_main = (float*)d_out;                                  // [B, MELMAX, D]
    float* out_dur  = (float*)d_out + (size_t)B_ * MELMAX_ * D_;      // [B, T]

    float *h1, *wt1, *wt2;
    int *idx;
    cudaGetSymbolAddress((void**)&h1,  g_h1);
    cudaGetSymbolAddress((void**)&wt1, g_wt1);
    cudaGetSymbolAddress((void**)&wt2, g_wt2);
    cudaGetSymbolAddress((void**)&idx, g_idx);

    // 1. transpose both conv weights
    transpose_w_kernel<<<2 * (KK_ * F_) / 256, 256>>>(conv1_w, wt1, conv2_w, wt2);

    // 2. cumsum + index expansion
    cumsum_idx_kernel<<<B_, T_>>>(target, idx);

    // 3. conv1 + LN + relu -> h1
    dim3 cgrid(T_ / TT, B_);
    conv_ln_relu_kernel<false><<<cgrid, 256>>>(x, wt1, conv1_b, ln1_g, ln1_b,
                                               nullptr, nullptr, h1);

    // 4. conv2 + LN + relu + dur head -> out_dur (h2 never materialized)
    conv_ln_relu_kernel<true><<<cgrid, 256>>>(h1, wt2, conv2_b, ln2_g, ln2_b,
                                              lin_w, lin_b, out_dur);

    // 5. length-regulator gather
    dim3 ggrid(MELMAX_ / 16, B_);
    gather_kernel<<<ggrid, 256>>>((const float4*)x, idx, (float4*)out_main);
}

// round 5
// speedup vs baseline: 2.4547x; 1.9076x over previous
#include <cuda_runtime.h>
#include <cuda_bf16.h>
#include <cstdint>

// Problem constants
#define B_  32
#define T_  512
#define D_  256
#define F_  256
#define MELMAX_ 2304
#define NTILES 128          // (B_*T_)/128 M-tiles

// smem geometry (bytes)
#define APITCH 144          // 64 bf16 + 8 pad (16B units shift by 9 -> ldmatrix conflict-free)
#define BPITCH 144
#define A_SZ   (128 * APITCH)      // 18432
#define B_SZ   (256 * BPITCH)      // 36864
#define STG    (2 * A_SZ + 2 * B_SZ)   // 110592 per stage
#define SMEM_DYN (2 * STG)             // 221184
#define SPITCH 264                 // epilogue stage pitch (floats)

// ---------------------------------------------------------------------------
// Scratch (no cudaMalloc allowed)
// ---------------------------------------------------------------------------
__device__ __nv_bfloat16 g_xh[B_ * T_ * D_];
__device__ __nv_bfloat16 g_xl[B_ * T_ * D_];
__device__ __nv_bfloat16 g_h1h[B_ * T_ * F_];
__device__ __nv_bfloat16 g_h1l[B_ * T_ * F_];
// weights: [conv][split][chunk(12)][f(256)][64] bf16, chunk = tap*4 + dblock
__device__ __nv_bfloat16 g_wb[2 * 2 * 12 * 256 * 64];
__device__ int g_idx[B_ * MELMAX_];

// ---------------------------------------------------------------------------
// PTX helpers (compute_80-level: cp.async, ldmatrix, mma.sync — valid on compute_103)
// ---------------------------------------------------------------------------
static __device__ __forceinline__ uint32_t smem_u32(const void* p) {
    uint32_t a;
    asm("{ .reg .u64 t; cvta.to.shared.u64 t, %1; cvt.u32.u64 %0, t; }" : "=r"(a) : "l"(p));
    return a;
}
static __device__ __forceinline__ void cp16(uint32_t saddr, const void* g, int srcsz) {
    asm volatile("cp.async.ca.shared.global [%0], [%1], 16, %2;"
                 :: "r"(saddr), "l"(g), "r"(srcsz) : "memory");
}
static __device__ __forceinline__ void cp_commit() {
    asm volatile("cp.async.commit_group;" ::: "memory");
}
template <int N>
static __device__ __forceinline__ void cp_wait() {
    asm volatile("cp.async.wait_group %0;" :: "n"(N) : "memory");
}
static __device__ __forceinline__ void ldsm_x4(uint32_t addr, uint32_t& r0, uint32_t& r1,
                                               uint32_t& r2, uint32_t& r3) {
    asm volatile("ldmatrix.sync.aligned.m8n8.x4.shared.b16 {%0,%1,%2,%3}, [%4];"
                 : "=r"(r0), "=r"(r1), "=r"(r2), "=r"(r3) : "r"(addr));
}
static __device__ __forceinline__ void mma_bf16(float* d, const uint32_t* a, const uint32_t* b) {
    asm volatile(
        "mma.sync.aligned.m16n8k16.row.col.f32.bf16.bf16.f32 "
        "{%0,%1,%2,%3}, {%4,%5,%6,%7}, {%8,%9}, {%0,%1,%2,%3};"
        : "+f"(d[0]), "+f"(d[1]), "+f"(d[2]), "+f"(d[3])
        : "r"(a[0]), "r"(a[1]), "r"(a[2]), "r"(a[3]), "r"(b[0]), "r"(b[1]));
}

// ---------------------------------------------------------------------------
// Prep: split x (fp32 -> bf16 hi/lo)
// ---------------------------------------------------------------------------
__global__ void split_x_kernel(const float4* __restrict__ x4,
                               __nv_bfloat162* __restrict__ xh2,
                               __nv_bfloat162* __restrict__ xl2) {
    int i = blockIdx.x * 256 + threadIdx.x;
    float4 v = x4[i];
    __nv_bfloat16 h0 = __float2bfloat16(v.x), h1 = __float2bfloat16(v.y);
    __nv_bfloat16 h2 = __float2bfloat16(v.z), h3 = __float2bfloat16(v.w);
    __nv_bfloat162 a, b, c, d;
    a.x = h0; a.y = h1; b.x = h2; b.y = h3;
    c.x = __float2bfloat16(v.x - __bfloat162float(h0));
    c.y = __float2bfloat16(v.y - __bfloat162float(h1));
    d.x = __float2bfloat16(v.z - __bfloat162float(h2));
    d.y = __float2bfloat16(v.w - __bfloat162float(h3));
    xh2[2 * i] = a; xh2[2 * i + 1] = b;
    xl2[2 * i] = c; xl2[2 * i + 1] = d;
}

// ---------------------------------------------------------------------------
// Prep: weights  w[f][d][tap] fp32 -> split-bf16 chunk layout
// ---------------------------------------------------------------------------
__global__ void prep_w_kernel(const float* __restrict__ w1, const float* __restrict__ w2,
                              __nv_bfloat16* __restrict__ wb) {
    int id = blockIdx.x * 256 + threadIdx.x;     // < 2*12*256*64
    int cv = id / 196608;
    int r = id - cv * 196608;
    int chunk = r >> 14;
    int rr = r & 16383;                          // f*64 + dc
    int f = rr >> 6, dc = rr & 63;
    int tap = chunk >> 2, db = chunk & 3;
    int d = db * 64 + dc;
    const float* w = cv ? w2 : w1;
    float v = w[(f * D_ + d) * 3 + tap];
    __nv_bfloat16 h = __float2bfloat16(v);
    __nv_bfloat16 l = __float2bfloat16(v - __bfloat162float(h));
    wb[(size_t)cv * 393216 + (size_t)chunk * 16384 + rr] = h;
    wb[(size_t)cv * 393216 + 196608 + (size_t)chunk * 16384 + rr] = l;
}

// ---------------------------------------------------------------------------
// Cumsum of durations + expansion to per-t_out source index (-1 past end)
// ---------------------------------------------------------------------------
__global__ void cumsum_idx_kernel(const int* __restrict__ target, int* __restrict__ idx) {
    __shared__ int s[T_];
    int b = blockIdx.x, t = threadIdx.x;
    s[t] = target[b * T_ + t];
    __syncthreads();
    for (int off = 1; off < T_; off <<= 1) {
        int v = (t >= off) ? s[t - off] : 0;
        __syncthreads();
        s[t] += v;
        __syncthreads();
    }
    int hi = s[t];
    int lo = (t > 0) ? s[t - 1] : 0;
    int* ib = idx + b * MELMAX_;
    for (int p = lo; p < hi && p < MELMAX_; p++) ib[p] = t;
    int total = s[T_ - 1];
    for (int p = total + t; p < MELMAX_; p += T_) ib[p] = -1;
}

// ---------------------------------------------------------------------------
// Warp-tile HMMA conv GEMM: Y[128,256] = im2col(X)[128,768] @ W^T, split-bf16
// MODE 0: LN+ReLU -> h (bf16 hi/lo).  MODE 1: LN+ReLU -> dot lin_w -> dur.
// grid: 128 M-tiles, block: 512 (16 warps = 4M x 4N, warp tile 32x64)
// ---------------------------------------------------------------------------
template <int MODE>
__global__ __launch_bounds__(512, 1) void conv_mma_kernel(
    const __nv_bfloat16* __restrict__ ah_g, const __nv_bfloat16* __restrict__ al_g,
    const __nv_bfloat16* __restrict__ wb,    // this conv's base
    const float* __restrict__ bias, const float* __restrict__ gamma,
    const float* __restrict__ beta,
    const float* __restrict__ lw, const float* __restrict__ lb,
    __nv_bfloat16* __restrict__ oh, __nv_bfloat16* __restrict__ ol,
    float* __restrict__ dur)
{
    extern __shared__ __align__(16) char smem[];
    __shared__ float sbi[256], sg[256], sbt[256], slw[256];
    const uint32_t sb = smem_u32(smem);
    const int tid = threadIdx.x;
    const int lane = tid & 31, wid = tid >> 5;
    const int wm = wid & 3, wn = wid >> 2;     // 4M x 4N warp grid
    const int tile = blockIdx.x;
    const int b = tile >> 2, t0 = (tile & 3) << 7;

    if (tid < 256) {
        sbi[tid] = bias[tid];
        sg[tid]  = gamma[tid];
        sbt[tid] = beta[tid];
        if (MODE == 1) slw[tid] = lw[tid];
    }

    // -------- chunk loader (cp.async, zero-fill at sequence edges) ----------
    auto load_chunk = [&](int c, int s) {
        const int tap = c >> 2, db = c & 3;
        const uint32_t stg = sb + s * STG;
        #pragma unroll
        for (int sp = 0; sp < 2; sp++) {
            const __nv_bfloat16* src = sp ? al_g : ah_g;
            #pragma unroll
            for (int i = 0; i < 2; i++) {
                int vid = tid + i * 512;              // 0..1023
                int row = vid >> 3, seg = vid & 7;
                int t = t0 + row + tap - 1;
                int ok = ((unsigned)t < (unsigned)T_) ? 16 : 0;
                int tc = min(max(t, 0), T_ - 1);
                const void* g = src + ((size_t)(b * T_ + tc) * D_ + db * 64 + seg * 8);
                cp16(stg + sp * A_SZ + row * APITCH + seg * 16, g, ok);
            }
        }
        #pragma unroll
        for (int sp = 0; sp < 2; sp++) {
            const __nv_bfloat16* src = wb + (size_t)(sp * 12 + c) * 16384;
            #pragma unroll
            for (int i = 0; i < 4; i++) {
                int vid = tid + i * 512;              // 0..2047
                int f = vid >> 3, seg = vid & 7;
                const void* g = src + f * 64 + seg * 8;
                cp16(stg + 2 * A_SZ + sp * B_SZ + f * BPITCH + seg * 16, g, 16);
            }
        }
        cp_commit();
    };

    float d[2][8][4];
    #pragma unroll
    for (int im = 0; im < 2; im++)
        #pragma unroll
        for (int n8 = 0; n8 < 8; n8++)
            #pragma unroll
            for (int q = 0; q < 4; q++) d[im][n8][q] = 0.0f;

    // per-lane ldmatrix base offsets
    const uint32_t a_row_off = (uint32_t)((wm * 32 + (lane & 15)) * APITCH + (lane >> 4) * 16);
    const uint32_t b_row_off = (uint32_t)((wn * 64 + (lane & 15)) * BPITCH + (lane >> 4) * 16);

    load_chunk(0, 0);
    load_chunk(1, 1);

    for (int c = 0; c < 12; c++) {
        if (c < 11) cp_wait<1>(); else cp_wait<0>();
        __syncthreads();

        const uint32_t stg = sb + (c & 1) * STG;
        const uint32_t a_h = stg + a_row_off;
        const uint32_t a_l = stg + A_SZ + a_row_off;
        const uint32_t b_h = stg + 2 * A_SZ + b_row_off;
        const uint32_t b_l = stg + 2 * A_SZ + B_SZ + b_row_off;

        #pragma unroll
        for (int k16 = 0; k16 < 4; k16++) {
            const uint32_t kb = k16 * 32;
            uint32_t ah[2][4], al[2][4], bb[8][2];
            #pragma unroll
            for (int im = 0; im < 2; im++) {
                ldsm_x4(a_h + im * 16 * APITCH + kb, ah[im][0], ah[im][1], ah[im][2], ah[im][3]);
                ldsm_x4(a_l + im * 16 * APITCH + kb, al[im][0], al[im][1], al[im][2], al[im][3]);
            }
            #pragma unroll
            for (int g = 0; g < 4; g++) {
                uint32_t r0, r1, r2, r3;
                ldsm_x4(b_h + g * 16 * BPITCH + kb, r0, r1, r2, r3);
                bb[2 * g][0] = r0; bb[2 * g][1] = r2;
                bb[2 * g + 1][0] = r1; bb[2 * g + 1][1] = r3;
            }
            #pragma unroll
            for (int im = 0; im < 2; im++)
                #pragma unroll
                for (int n8 = 0; n8 < 8; n8++) {
                    mma_bf16(d[im][n8], ah[im], bb[n8]);
                    mma_bf16(d[im][n8], al[im], bb[n8]);
                }
            #pragma unroll
            for (int g = 0; g < 4; g++) {
                uint32_t r0, r1, r2, r3;
                ldsm_x4(b_l + g * 16 * BPITCH + kb, r0, r1, r2, r3);
                bb[2 * g][0] = r0; bb[2 * g][1] = r2;
                bb[2 * g + 1][0] = r1; bb[2 * g + 1][1] = r3;
            }
            #pragma unroll
            for (int im = 0; im < 2; im++)
                #pragma unroll
                for (int n8 = 0; n8 < 8; n8++)
                    mma_bf16(d[im][n8], ah[im], bb[n8]);
        }
        __syncthreads();
        if (c + 2 < 12) load_chunk(c + 2, c & 1);
    }

    // ---------------- epilogue: stage accum -> LN + ReLU ----------------
    float* stage = (float*)smem;                 // [128][SPITCH]
    __syncthreads();
    {
        const int g = lane >> 2, q = lane & 3;
        #pragma unroll
        for (int im = 0; im < 2; im++)
            #pragma unroll
            for (int n8 = 0; n8 < 8; n8++) {
                int row = wm * 32 + im * 16 + g;
                int col = wn * 64 + n8 * 8 + q * 2;
                stage[row * SPITCH + col]           = d[im][n8][0];
                stage[row * SPITCH + col + 1]       = d[im][n8][1];
                stage[(row + 8) * SPITCH + col]     = d[im][n8][2];
                stage[(row + 8) * SPITCH + col + 1] = d[im][n8][3];
            }
    }
    __syncthreads();

    {
        const int row = tid >> 2, sub = tid & 3;     // 128 rows x 4 threads
        const float* srow = stage + row * SPITCH + sub * 64;
        float s1 = 0.f, s2 = 0.f;
        #pragma unroll
        for (int j = 0; j < 64; j++) {
            float v = srow[j] + sbi[sub * 64 + j];
            s1 += v; s2 += v * v;
        }
        s1 += __shfl_xor_sync(0xFFFFFFFFu, s1, 1);
        s2 += __shfl_xor_sync(0xFFFFFFFFu, s2, 1);
        s1 += __shfl_xor_sync(0xFFFFFFFFu, s1, 2);
        s2 += __shfl_xor_sync(0xFFFFFFFFu, s2, 2);
        float mu  = s1 * (1.0f / 256.0f);
        float var = s2 * (1.0f / 256.0f) - mu * mu;
        float inv = rsqrtf(var + 1e-5f);

        if (MODE == 0) {
            __nv_bfloat162* oh2 = (__nv_bfloat162*)oh;
            __nv_bfloat162* ol2 = (__nv_bfloat162*)ol;
            const size_t obase = ((size_t)(b * T_ + t0 + row)) * 128 + sub * 32;
            #pragma unroll
            for (int j = 0; j < 32; j++) {
                int c0 = sub * 64 + 2 * j;
                float v0 = srow[2 * j]     + sbi[c0];
                float v1 = srow[2 * j + 1] + sbi[c0 + 1];
                float y0 = fmaxf((v0 - mu) * inv * sg[c0]     + sbt[c0],     0.0f);
                float y1 = fmaxf((v1 - mu) * inv * sg[c0 + 1] + sbt[c0 + 1], 0.0f);
                __nv_bfloat16 h0 = __float2bfloat16(y0);
                __nv_bfloat16 h1 = __float2bfloat16(y1);
                __nv_bfloat162 hh, ll;
                hh.x = h0; hh.y = h1;
                ll.x = __float2bfloat16(y0 - __bfloat162float(h0));
                ll.y = __float2bfloat16(y1 - __bfloat162float(h1));
                oh2[obase + j] = hh;
                ol2[obase + j] = ll;
            }
        } else {
            float sd = 0.f;
            #pragma unroll
            for (int j = 0; j < 64; j++) {
                int cc = sub * 64 + j;
                float v = srow[j] + sbi[cc];
                float y = fmaxf((v - mu) * inv * sg[cc] + sbt[cc], 0.0f);
                sd += y * slw[cc];
            }
            sd += __shfl_xor_sync(0xFFFFFFFFu, sd, 1);
            sd += __shfl_xor_sync(0xFFFFFFFFu, sd, 2);
            if (sub == 0) dur[(size_t)b * T_ + t0 + row] = fmaxf(sd + lb[0], 0.0f);
        }
    }
}

// ---------------------------------------------------------------------------
// Length-regulator gather via precomputed idx (float4 streaming)
// ---------------------------------------------------------------------------
__global__ __launch_bounds__(256) void gather_kernel(
    const float4* __restrict__ x4, const int* __restrict__ idx, float4* __restrict__ out4) {
    const int b = blockIdx.y;
    const int f4 = threadIdx.x & 63;
    const int trow = threadIdx.x >> 6;
    const int t0 = blockIdx.x * 16;
    const float4 z = make_float4(0.f, 0.f, 0.f, 0.f);
    #pragma unroll
    for (int i = 0; i < 4; i++) {
        int t = t0 + i * 4 + trow;
        int j = idx[b * MELMAX_ + t];
        float4 v = (j >= 0) ? x4[((size_t)b * T_ + j) * 64 + f4] : z;
        out4[((size_t)b * MELMAX_ + t) * 64 + f4] = v;
    }
}

// ---------------------------------------------------------------------------
extern "C" void kernel_launch(void* const* d_in, const int* in_sizes, int n_in,
                              void* d_out, int out_size) {
    int base = 2;
    if (n_in >= 3 && in_sizes[2] == 1) base = 3;   // scalar mel_max_length present

    const float* x       = (const float*)d_in[0];
    const int*   target  = (const int*)  d_in[1];
    const float* conv1_w = (const float*)d_in[base + 0];
    const float* conv1_b = (const float*)d_in[base + 1];
    const float* ln1_g   = (const float*)d_in[base + 2];
    const float* ln1_b   = (const float*)d_in[base + 3];
    const float* conv2_w = (const float*)d_in[base + 4];
    const float* conv2_b = (const float*)d_in[base + 5];
    const float* ln2_g   = (const float*)d_in[base + 6];
    const float* ln2_b   = (const float*)d_in[base + 7];
    const float* lin_w   = (const float*)d_in[base + 8];
    const float* lin_b   = (const float*)d_in[base + 9];

    float* out_main = (float*)d_out;                                  // [B, MELMAX, D]
    float* out_dur  = (float*)d_out + (size_t)B_ * MELMAX_ * D_;      // [B, T]

    __nv_bfloat16 *xh, *xl, *h1h, *h1l, *wbp;
    int* idx;
    cudaGetSymbolAddress((void**)&xh,  g_xh);
    cudaGetSymbolAddress((void**)&xl,  g_xl);
    cudaGetSymbolAddress((void**)&h1h, g_h1h);
    cudaGetSymbolAddress((void**)&h1l, g_h1l);
    cudaGetSymbolAddress((void**)&wbp, g_wb);
    cudaGetSymbolAddress((void**)&idx, g_idx);

    cudaFuncSetAttribute(conv_mma_kernel<0>, cudaFuncAttributeMaxDynamicSharedMemorySize, SMEM_DYN);
    cudaFuncSetAttribute(conv_mma_kernel<1>, cudaFuncAttributeMaxDynamicSharedMemorySize, SMEM_DYN);

    // 1. split x into bf16 hi/lo
    split_x_kernel<<<(B_ * T_ * D_ / 4) / 256, 256>>>((const float4*)x,
                                                      (__nv_bfloat162*)xh, (__nv_bfloat162*)xl);
    // 2. prep weights (both convs)
    prep_w_kernel<<<(2 * 12 * 256 * 64) / 256, 256>>>(conv1_w, conv2_w, wbp);
    // 3. cumsum + index expansion
    cumsum_idx_kernel<<<B_, T_>>>(target, idx);

    // 4. conv1 -> h1 split-bf16
    conv_mma_kernel<0><<<NTILES, 512, SMEM_DYN>>>(xh, xl, wbp, conv1_b, ln1_g, ln1_b,
                                                  nullptr, nullptr, h1h, h1l, nullptr);
    // 5. conv2 + dur head -> out_dur
    conv_mma_kernel<1><<<NTILES, 512, SMEM_DYN>>>(h1h, h1l, wbp + (size_t)393216,
                                                  conv2_b, ln2_g, ln2_b,
                                                  lin_w, lin_b, nullptr, nullptr, out_dur);
    // 6. length-regulator gather
    dim3 ggrid(MELMAX_ / 16, B_);
    gather_kernel<<<ggrid, 256>>>((const float4*)x, idx, (float4*)out_main);
}